// round 13
// baseline (speedup 1.0000x reference)
#include <cuda_runtime.h>
#include <cuda_fp16.h>
#include <cstdint>

#define BB 2
#define NQ 512
#define NK 512
#define D_FF 128

#define QT2 (NQ / 16)
#define KT2 (NK / 16)
#define N_TILES2 (BB * QT2 * KT2)   /* 2048 double-tiles (16q x 16k = 256 pairs) */
#define N_BLOCKS 148
#define NTHR 512

// Per-row GEMM-1 halves (b1 folded into qc)
__device__ float g_qc[BB * NQ * D_FF];
__device__ float g_kc[BB * NK * D_FF];

// ---------------------------------------------------------------------------
// Prep kernel: blocks [0,1024) -> q rows, [1024,2048) -> k rows.
// ---------------------------------------------------------------------------
__global__ void prep_kernel(const float* __restrict__ q_inv,
                            const float* __restrict__ k_inv,
                            const float* __restrict__ Wq,
                            const float* __restrict__ bq,
                            const float* __restrict__ Wk,
                            const float* __restrict__ bk,
                            const float* __restrict__ W1,
                            const float* __restrict__ b1) {
    int bid = blockIdx.x;
    int t = threadIdx.x;
    __shared__ float msg[64];
    if (bid < BB * NQ) {
        int row = bid;
        if (t < 64) {
            const float* qi = q_inv + (size_t)row * 128;
            float a0 = bq[t], a1 = 0.f;
            #pragma unroll 4
            for (int i = 0; i < 128; i += 2) {
                a0 = fmaf(qi[i],     Wq[i * 64 + t],       a0);
                a1 = fmaf(qi[i + 1], Wq[(i + 1) * 64 + t], a1);
            }
            msg[t] = a0 + a1;
        }
        __syncthreads();
        float a0 = b1[t], a1 = 0.f;
        #pragma unroll 4
        for (int m = 0; m < 64; m += 2) {
            a0 = fmaf(msg[m],     W1[m * 128 + t],       a0);
            a1 = fmaf(msg[m + 1], W1[(m + 1) * 128 + t], a1);
        }
        g_qc[(size_t)row * 128 + t] = a0 + a1;
    } else {
        int row = bid - BB * NQ;
        if (t < 64) {
            const float* ki = k_inv + (size_t)row * 128;
            float a0 = bk[t], a1 = 0.f;
            #pragma unroll 4
            for (int i = 0; i < 128; i += 2) {
                a0 = fmaf(ki[i],     Wk[i * 64 + t],       a0);
                a1 = fmaf(ki[i + 1], Wk[(i + 1) * 64 + t], a1);
            }
            msg[t] = a0 + a1;
        }
        __syncthreads();
        float a0 = 0.f, a1 = 0.f;
        #pragma unroll 4
        for (int m = 0; m < 64; m += 2) {
            a0 = fmaf(msg[m],     W1[(64 + m) * 128 + t],     a0);
            a1 = fmaf(msg[m + 1], W1[(64 + m + 1) * 128 + t], a1);
        }
        g_kc[(size_t)row * 128 + t] = a0 + a1;
    }
}

// ---------------------------------------------------------------------------
// fp16 mma helpers
// ---------------------------------------------------------------------------
// Byte offset of logical column c (halves) within a row: columns grouped by 16,
// permuted so thread t's fragment {2t,2t+1,8+2t,8+2t+1} is contiguous (8 bytes).
__device__ __forceinline__ int colb(int c) {
    int r = c & 15;
    int pos = ((r & 6) << 1) + ((r >> 3) & 1) * 2 + (r & 1);
    return ((c >> 4) << 5) + pos * 2;
}
__device__ __forceinline__ uint32_t f2h2(float lo, float hi) {
    __half2 h = __floats2half2_rn(lo, hi);
    return *reinterpret_cast<uint32_t*>(&h);
}
__device__ __forceinline__ void mma16(float* d,
                                      uint32_t a0, uint32_t a1, uint32_t a2,
                                      uint32_t a3, uint32_t b0, uint32_t b1) {
    asm("mma.sync.aligned.m16n8k16.row.col.f32.f16.f16.f32 "
        "{%0,%1,%2,%3}, {%4,%5,%6,%7}, {%8,%9}, {%0,%1,%2,%3};"
        : "+f"(d[0]), "+f"(d[1]), "+f"(d[2]), "+f"(d[3])
        : "r"(a0), "r"(a1), "r"(a2), "r"(a3), "r"(b0), "r"(b1));
}

// ---------------------------------------------------------------------------
// SMEM layout (byte offsets). Row strides 160/288 bytes (==32 mod 128) make
// every fragment LDS.64 bank-conflict-free (8g+2t covers all 32 banks/phase).
// ---------------------------------------------------------------------------
#define SW1T 0                 /* 128 n-rows x 160 B (64 k halves)  */
#define SW2T 20480             /* 64  n-rows x 288 B (128 k halves) */
#define SA   38912             /* 256 m-rows x 160 B (64 halves)    */
#define SH   79872             /* 256 m-rows x 288 B (128 halves)   */
#define QCS  153600            /* 16 x 136 f32 */
#define KCS  162304            /* 16 x 136 f32 */
#define QES  171008            /* 16 x 97 f32  */
#define KES  177216            /* 16 x 97 f32  */
#define B2S  183424            /* 64 f32 */
#define SMEM_TOTAL 183680

__global__ __launch_bounds__(NTHR, 1)
void pair_mma_kernel(const float* __restrict__ q_equi,
                     const float* __restrict__ k_equi,
                     const float* __restrict__ W1,
                     const float* __restrict__ W2,
                     const float* __restrict__ b2,
                     float* __restrict__ out) {
    extern __shared__ char smc[];
    float* b2s = (float*)(smc + B2S);

    const int tid = threadIdx.x;

    // ---- one-time static staging: W1 pairwise rows + W2 as fp16, k-contig ----
    for (int i = tid; i < 128 * 64; i += NTHR) {     // sW1T[n][c] = W1[128+c][n]
        int n = i >> 6, c = i & 63;
        *(__half*)(smc + SW1T + n * 160 + colb(c)) =
            __float2half_rn(W1[(128 + c) * D_FF + n]);
    }
    for (int i = tid; i < 64 * 128; i += NTHR) {     // sW2T[n][k] = W2[k][n]
        int n = i >> 7, k = i & 127;
        *(__half*)(smc + SW2T + n * 288 + colb(k)) =
            __float2half_rn(W2[k * 64 + n]);
    }
    if (tid < 64) b2s[tid] = b2[tid];

    const int warp = tid >> 5, lane = tid & 31;
    const int wm = warp >> 1, wn = warp & 1;     // 8 m-strips(32) x 2 n-strips
    const int g = lane >> 2, t = lane & 3;
    const int m0 = wm * 32;

    const int fp = tid >> 1, fh = tid & 1;       // feature phase: 2 thr/pair
    const int fql = fp >> 4, fkl = fp & 15;

    for (int tile = blockIdx.x; tile < N_TILES2; tile += N_BLOCKS) {
        const int b  = tile / (QT2 * KT2);
        const int r  = tile % (QT2 * KT2);
        const int q0 = (r / KT2) * 16;
        const int k0 = (r % KT2) * 16;

        __syncthreads();   // prev iteration fully consumed dynamic buffers

        // ---- per-tile staging: qc/kc (f32) + equi tiles ----
        float* qcs = (float*)(smc + QCS);
        float* kcs = (float*)(smc + KCS);
        for (int i = tid; i < 16 * 128; i += NTHR)
            qcs[(i >> 7) * 136 + (i & 127)] =
                g_qc[(size_t)(b * NQ + q0 + (i >> 7)) * D_FF + (i & 127)];
        for (int i = tid; i < 16 * 128; i += NTHR)
            kcs[(i >> 7) * 136 + (i & 127)] =
                g_kc[(size_t)(b * NK + k0 + (i >> 7)) * D_FF + (i & 127)];
        float* qes = (float*)(smc + QES);
        float* kes = (float*)(smc + KES);
        for (int i = tid; i < 16 * 96; i += NTHR)
            qes[(i / 96) * 97 + (i % 96)] = q_equi[(size_t)(b * NQ + q0) * 96 + i];
        for (int i = tid; i < 16 * 96; i += NTHR)
            kes[(i / 96) * 97 + (i % 96)] = k_equi[(size_t)(b * NK + k0) * 96 + i];
        __syncthreads();

        // ---- features -> sA as fp16 (dot cols 0..31, dist cols 32..63) ----
        {
            const float* qr = qes + fql * 97;    // warp-uniform row
            const float* kr = kes + fkl * 97;
            char* ar = smc + SA + fp * 160;
            #pragma unroll
            for (int e = 16 * fh; e < 16 * fh + 16; e += 2) {
                float qa0 = qr[e], qb0 = qr[32 + e], qc0 = qr[64 + e];
                float ka0 = kr[e], kb0 = kr[32 + e], kc0 = kr[64 + e];
                float qa1 = qr[e + 1], qb1 = qr[33 + e], qc1 = qr[65 + e];
                float ka1 = kr[e + 1], kb1 = kr[33 + e], kc1 = kr[65 + e];
                float dot0 = qa0 * ka0 + qb0 * kb0 + qc0 * kc0;
                float dot1 = qa1 * ka1 + qb1 * kb1 + qc1 * kc1;
                float d0 = qa0 - ka0, d1 = qb0 - kb0, d2 = qc0 - kc0;
                float e0 = qa1 - ka1, e1 = qb1 - kb1, e2 = qc1 - kc1;
                float dist0 = sqrtf(d0 * d0 + d1 * d1 + d2 * d2);
                float dist1 = sqrtf(e0 * e0 + e1 * e1 + e2 * e2);
                *(uint32_t*)(ar + colb(e))      = f2h2(dot0, dot1);
                *(uint32_t*)(ar + colb(32 + e)) = f2h2(dist0, dist1);
            }
        }
        __syncthreads();

        // ---- GEMM-1: rows m0..m0+31, cols wn*64..+64, K=64 (4 k-slabs) ----
        float acc1[2][8][4];
        #pragma unroll
        for (int mt = 0; mt < 2; mt++)
            #pragma unroll
            for (int nt = 0; nt < 8; nt++)
                #pragma unroll
                for (int rr = 0; rr < 4; rr++) acc1[mt][nt][rr] = 0.f;

        #pragma unroll
        for (int kk = 0; kk < 4; kk++) {
            uint2 aLo[2], aHi[2];
            #pragma unroll
            for (int mt = 0; mt < 2; mt++) {
                const char* ap = smc + SA + (m0 + mt * 16 + g) * 160 + kk * 32 + t * 8;
                aLo[mt] = *(const uint2*)ap;
                aHi[mt] = *(const uint2*)(ap + 8 * 160);
            }
            #pragma unroll
            for (int nt = 0; nt < 8; nt++) {
                uint2 bf = *(const uint2*)(smc + SW1T +
                                           (wn * 64 + nt * 8 + g) * 160 + kk * 32 + t * 8);
                mma16(acc1[0][nt], aLo[0].x, aHi[0].x, aLo[0].y, aHi[0].y, bf.x, bf.y);
                mma16(acc1[1][nt], aLo[1].x, aHi[1].x, aLo[1].y, aHi[1].y, bf.x, bf.y);
            }
        }

        // ---- epilogue 1: +qc +kc, silu, fp16 -> sH ----
        #pragma unroll
        for (int mt = 0; mt < 2; mt++) {
            const float* qrow = qcs + (wm * 2 + mt) * 136;   // warp-uniform
            const float* kr0  = kcs + g * 136;
            const float* kr1  = kcs + (g + 8) * 136;
            char* h0p = smc + SH + (m0 + mt * 16 + g) * 288;
            char* h1p = h0p + 8 * 288;
            #pragma unroll
            for (int nt = 0; nt < 8; nt++) {
                int nb = wn * 64 + nt * 8 + 2 * t;
                float2 qv  = *(const float2*)(qrow + nb);
                float2 kv0 = *(const float2*)(kr0 + nb);
                float2 kv1 = *(const float2*)(kr1 + nb);
                float h0 = acc1[mt][nt][0] + qv.x + kv0.x;
                float h1 = acc1[mt][nt][1] + qv.y + kv0.y;
                float h2 = acc1[mt][nt][2] + qv.x + kv1.x;
                float h3 = acc1[mt][nt][3] + qv.y + kv1.y;
                h0 = __fdividef(h0, 1.f + __expf(-h0));
                h1 = __fdividef(h1, 1.f + __expf(-h1));
                h2 = __fdividef(h2, 1.f + __expf(-h2));
                h3 = __fdividef(h3, 1.f + __expf(-h3));
                int gb = ((wn * 4 + (nt >> 1)) << 5) + t * 8 + (nt & 1) * 4;
                *(uint32_t*)(h0p + gb) = f2h2(h0, h1);
                *(uint32_t*)(h1p + gb) = f2h2(h2, h3);
            }
        }
        __syncthreads();

        // ---- GEMM-2: rows m0..m0+31, cols wn*32..+32, K=128 (8 k-slabs) ----
        float acc2[2][4][4];
        #pragma unroll
        for (int mt = 0; mt < 2; mt++)
            #pragma unroll
            for (int nt = 0; nt < 4; nt++)
                #pragma unroll
                for (int rr = 0; rr < 4; rr++) acc2[mt][nt][rr] = 0.f;

        #pragma unroll
        for (int kk = 0; kk < 8; kk++) {
            uint2 aLo[2], aHi[2];
            #pragma unroll
            for (int mt = 0; mt < 2; mt++) {
                const char* ap = smc + SH + (m0 + mt * 16 + g) * 288 + kk * 32 + t * 8;
                aLo[mt] = *(const uint2*)ap;
                aHi[mt] = *(const uint2*)(ap + 8 * 288);
            }
            #pragma unroll
            for (int nt = 0; nt < 4; nt++) {
                uint2 bf = *(const uint2*)(smc + SW2T +
                                           (wn * 32 + nt * 8 + g) * 288 + kk * 32 + t * 8);
                mma16(acc2[0][nt], aLo[0].x, aHi[0].x, aLo[0].y, aHi[0].y, bf.x, bf.y);
                mma16(acc2[1][nt], aLo[1].x, aHi[1].x, aLo[1].y, aHi[1].y, bf.x, bf.y);
            }
        }

        // ---- epilogue 2: +b2, direct store (row p: jq=p>>4, jk=p&15) ----
        #pragma unroll
        for (int nt = 0; nt < 4; nt++) {
            int nb = wn * 32 + nt * 8 + 2 * t;
            float2 bb = *(const float2*)(b2s + nb);
            #pragma unroll
            for (int mt = 0; mt < 2; mt++) {
                int p0 = m0 + mt * 16 + g;
                int p1 = p0 + 8;
                size_t o0 = ((size_t)(b * NQ + q0 + (p0 >> 4)) * NK + (k0 + (p0 & 15))) * 64 + nb;
                size_t o1 = ((size_t)(b * NQ + q0 + (p1 >> 4)) * NK + (k0 + (p1 & 15))) * 64 + nb;
                *(float2*)(out + o0) =
                    make_float2(acc2[mt][nt][0] + bb.x, acc2[mt][nt][1] + bb.y);
                *(float2*)(out + o1) =
                    make_float2(acc2[mt][nt][2] + bb.x, acc2[mt][nt][3] + bb.y);
            }
        }
    }
}

// ---------------------------------------------------------------------------
extern "C" void kernel_launch(void* const* d_in, const int* in_sizes, int n_in,
                              void* d_out, int out_size) {
    const float* q_equi = (const float*)d_in[0];
    const float* q_inv  = (const float*)d_in[1];
    const float* k_equi = (const float*)d_in[2];
    const float* k_inv  = (const float*)d_in[3];
    const float* Wq     = (const float*)d_in[4];
    const float* bq     = (const float*)d_in[5];
    const float* Wk     = (const float*)d_in[6];
    const float* bk     = (const float*)d_in[7];
    const float* W1     = (const float*)d_in[8];
    const float* b1     = (const float*)d_in[9];
    const float* W2     = (const float*)d_in[10];
    const float* b2     = (const float*)d_in[11];
    float* out = (float*)d_out;

    static int smem_set = 0;
    if (!smem_set) {
        cudaFuncSetAttribute(pair_mma_kernel,
                             cudaFuncAttributeMaxDynamicSharedMemorySize,
                             SMEM_TOTAL);
        smem_set = 1;
    }

    prep_kernel<<<BB * (NQ + NK), 128>>>(q_inv, k_inv, Wq, bq, Wk, bk, W1, b1);
    pair_mma_kernel<<<N_BLOCKS, NTHR, SMEM_TOTAL>>>(
        q_equi, k_equi, W1, W2, b2, out);
}